// round 16
// baseline (speedup 1.0000x reference)
#include <cuda_runtime.h>
#include <cuda_fp16.h>
#include <stdint.h>
#include <math.h>

#define C_CH  256
#define OUT_H 7
#define OUT_W 35
#define ENTRIES (OUT_W * 4 * 4)   // 560 descriptors per (roi, ph)

// -------- channel-last fp16 scratch (static: allocation-free) --------
__device__ __half g_h0[(size_t)2 * 256 * 256 * 256];  // 67MB
__device__ __half g_h1[(size_t)2 * 256 * 128 * 128];  // 16.8MB
__device__ __half g_h2[(size_t)2 * 256 *  64 *  64];  // 4.2MB
__device__ __half g_h3[(size_t)2 * 256 *  32 *  32];  // 1.05MB

#define NB0 16384
#define NB1 4096
#define NB2 1024
#define NB3 256
#define NB_ALL (NB0 + NB1 + NB2 + NB3)

// Fused NCHW fp32 -> NHWC fp16 transpose for all 4 levels, 1D grid.
__global__ __launch_bounds__(256)
void transpose_all_kernel(const float* __restrict__ f0,
                          const float* __restrict__ f1,
                          const float* __restrict__ f2,
                          const float* __restrict__ f3)
{
    __shared__ float tile[64][33];
    const int bid = blockIdx.x;
    int lev, rel;
    if      (bid < NB0)             { lev = 0; rel = bid; }
    else if (bid < NB0 + NB1)       { lev = 1; rel = bid - NB0; }
    else if (bid < NB0 + NB1 + NB2) { lev = 2; rel = bid - NB0 - NB1; }
    else                            { lev = 3; rel = bid - NB0 - NB1 - NB2; }

    const int Hc  = 256 >> lev;
    const int HW  = Hc * Hc;
    const int pxb = HW / 32;
    const int p0  = (rel % pxb) * 32;
    const int t   = rel / pxb;          // 0..7
    const int c0  = (t & 3) * 64;
    const int b   = t >> 2;

    const float* __restrict__ in = (lev == 0) ? f0 : (lev == 1) ? f1
                                 : (lev == 2) ? f2 : f3;
    __half* __restrict__ outp = (lev == 0) ? g_h0 : (lev == 1) ? g_h1
                              : (lev == 2) ? g_h2 : g_h3;

    const int tx = threadIdx.x;
    const int ty = threadIdx.y;

    const float* __restrict__ ip = in + ((size_t)b * C_CH + c0) * HW + p0;
    #pragma unroll
    for (int k = 0; k < 8; ++k) {
        const int c = ty + 8 * k;
        tile[c][tx] = __ldg(ip + (size_t)c * HW + tx);
    }
    __syncthreads();

    const int tid = ty * 32 + tx;
    const int cl  = tid & 31;            // channel pair
    const int r   = tid >> 5;            // 0..7
    __half2* __restrict__ op =
        (__half2*)(outp + ((size_t)b * HW + p0) * C_CH + c0) + cl;
    #pragma unroll
    for (int m = 0; m < 4; ++m) {
        const int pix = r + 8 * m;
        op[(size_t)pix * (C_CH / 2)] =
            __floats2half2_rn(tile[2 * cl][pix], tile[2 * cl + 1][pix]);
    }
}

__device__ __forceinline__ unsigned int h2_as_u32(__half2 h)
{
    return *(unsigned int*)&h;
}
__device__ __forceinline__ __half2 u32_as_h2(unsigned int u)
{
    return *(__half2*)&u;
}

// One fp16 tap over all 256 channels: lane owns 8 ch (uint4 = 16B).
__device__ __forceinline__ void tap4(const uint4* __restrict__ T,
                                     int p, __half2 w, __half2 a[4])
{
    const uint4 r = __ldg(T + p);
    a[0] = __hfma2(w, u32_as_h2(r.x), a[0]);
    a[1] = __hfma2(w, u32_as_h2(r.y), a[1]);
    a[2] = __hfma2(w, u32_as_h2(r.z), a[2]);
    a[3] = __hfma2(w, u32_as_h2(r.w), a[3]);
}

// -------- main kernel: block = (roi n, ph), 160 threads = 5 warps --------
// warp w handles pw = w*7 .. w*7+6; lane owns 8 consecutive channels.
// One LDG.128 per tap covers all 256 channels.
__global__ __launch_bounds__(160, 6)
void rroi_main_kernel(const float* __restrict__ rois, float* __restrict__ out)
{
    __shared__ int4         s_pix[ENTRIES];      // tap pixel idx, uint4 units
    __shared__ uint4        s_wt[ENTRIES];       // 4 dup'd half2 weights
    __shared__ unsigned int s_outh[OUT_W * 130]; // [pw][c/2] half2, 128+2 pad

    const int n    = blockIdx.x;
    const int ph   = blockIdx.y;
    const int tid  = threadIdx.x;
    const int lane = tid & 31;
    const int wrp  = tid >> 5;          // 0..4

    const float r1 = __ldg(rois + n * 6 + 1);
    const float r2 = __ldg(rois + n * 6 + 2);
    const float r3 = __ldg(rois + n * 6 + 3);
    const float r4 = __ldg(rois + n * 6 + 4);
    const float r5 = __ldg(rois + n * 6 + 5);
    const int   b  = (int)__ldg(rois + n * 6 + 0);
    float sint, cost;
    sincosf(r5, &sint, &cost);

    const uint4* __restrict__ T0 = (const uint4*)g_h0;
    const uint4* __restrict__ T1 = (const uint4*)g_h1;
    const uint4* __restrict__ T2 = (const uint4*)g_h2;
    const uint4* __restrict__ T3 = (const uint4*)g_h3;

    // ---- Phase 1: descriptors ----
    for (int e = tid; e < ENTRIES; e += 160) {
        const int pw  = e % OUT_W;
        const int q   = e / OUT_W;
        const int lev = q >> 2;
        const int s   = q & 3;
        const int sy  = s >> 1;
        const int sx  = s & 1;

        const int   Hc = 256 >> lev;
        const int   HW = Hc * Hc;
        const float sc = 0.25f / (float)(1 << lev);

        const float cx = r1 * sc;
        const float cy = r2 * sc;
        const float w  = fmaxf(r3 * sc, 1.0f);
        const float h  = fmaxf(r4 * sc, 1.0f);

        const float gy = (float)ph + ((float)sy + 0.5f) * 0.5f;
        const float gx = (float)pw + ((float)sx + 0.5f) * 0.5f;
        const float yy = gy * (h * (1.0f / OUT_H)) - 0.5f * h;
        const float xx = gx * (w * (1.0f / OUT_W)) - 0.5f * w;

        float x = xx * cost - yy * sint + cx;
        float y = xx * sint + yy * cost + cy;

        const float Hf = (float)Hc;
        const bool valid = (y >= -1.0f) && (y <= Hf) && (x >= -1.0f) && (x <= Hf);
        y = fminf(fmaxf(y, 0.0f), Hf - 1.0f);
        x = fminf(fmaxf(x, 0.0f), Hf - 1.0f);

        const int y0 = (int)floorf(y);
        const int x0 = (int)floorf(x);
        const int y1 = min(y0 + 1, Hc - 1);
        const int x1 = min(x0 + 1, Hc - 1);
        const float ly = y - (float)y0;
        const float lx = x - (float)x0;
        const float hy = 1.0f - ly;
        const float hx = 1.0f - lx;
        const float qv = valid ? 0.25f : 0.0f;

        const int base = b * HW;
        // uint4 units: 256 ch * 2B / 16B = 32 per pixel
        s_pix[e] = make_int4((base + y0 * Hc + x0) * 32,
                             (base + y0 * Hc + x1) * 32,
                             (base + y1 * Hc + x0) * 32,
                             (base + y1 * Hc + x1) * 32);
        s_wt[e] = make_uint4(h2_as_u32(__float2half2_rn(hy * hx * qv)),
                             h2_as_u32(__float2half2_rn(hy * lx * qv)),
                             h2_as_u32(__float2half2_rn(ly * hx * qv)),
                             h2_as_u32(__float2half2_rn(ly * lx * qv)));
    }
    __syncthreads();

    // ---- Phase 2: gathers (one LDG.128 per tap, 256 ch) ----
    #pragma unroll
    for (int pwi = 0; pwi < 7; ++pwi) {
        const int pw = wrp * 7 + pwi;
        __half2 best[4];
        #pragma unroll
        for (int lev = 0; lev < 4; ++lev) {
            const uint4* __restrict__ T =
                (lev == 0) ? T0 : (lev == 1) ? T1 : (lev == 2) ? T2 : T3;
            float acc[8] = {0.f, 0.f, 0.f, 0.f, 0.f, 0.f, 0.f, 0.f};
            #pragma unroll
            for (int s2 = 0; s2 < 2; ++s2) {   // 2 samples per half2 chain
                __half2 a[4];
                a[0] = __float2half2_rn(0.f);
                a[1] = a[0]; a[2] = a[0]; a[3] = a[0];
                #pragma unroll
                for (int ss = 0; ss < 2; ++ss) {
                    const int e = (lev * 4 + s2 * 2 + ss) * OUT_W + pw;
                    const int4  p = s_pix[e];
                    const uint4 w = s_wt[e];
                    tap4(T, p.x + lane, u32_as_h2(w.x), a);
                    tap4(T, p.y + lane, u32_as_h2(w.y), a);
                    tap4(T, p.z + lane, u32_as_h2(w.z), a);
                    tap4(T, p.w + lane, u32_as_h2(w.w), a);
                }
                #pragma unroll
                for (int k = 0; k < 4; ++k) {
                    const float2 f = __half22float2(a[k]);
                    acc[2 * k]     += f.x;
                    acc[2 * k + 1] += f.y;
                }
            }
            #pragma unroll
            for (int k = 0; k < 4; ++k) {
                const __half2 h2 = __floats2half2_rn(acc[2 * k], acc[2 * k + 1]);
                best[k] = (lev == 0) ? h2 : __hmax2(best[k], h2);
            }
        }
        // lane owns channels lane*8..lane*8+7 -> half2 words lane*4..lane*4+3
        #pragma unroll
        for (int k = 0; k < 4; ++k)
            s_outh[pw * 130 + lane * 4 + k] = h2_as_u32(best[k]);
    }
    __syncthreads();

    // ---- Phase 3: coalesced fp32 output write ----
    float* __restrict__ ob = out + (((size_t)n * C_CH) * OUT_H + ph) * OUT_W;
    for (int idx = tid; idx < C_CH * OUT_W; idx += 160) {
        const int c  = idx / OUT_W;
        const int pw = idx - c * OUT_W;
        const __half2 hv = u32_as_h2(s_outh[pw * 130 + (c >> 1)]);
        ob[(size_t)c * (OUT_H * OUT_W) + pw] =
            (c & 1) ? __high2float(hv) : __low2float(hv);
    }
}

extern "C" void kernel_launch(void* const* d_in, const int* in_sizes, int n_in,
                              void* d_out, int out_size)
{
    const float* f0   = (const float*)d_in[0];
    const float* f1   = (const float*)d_in[1];
    const float* f2   = (const float*)d_in[2];
    const float* f3   = (const float*)d_in[3];
    const float* rois = (const float*)d_in[4];
    float* out = (float*)d_out;

    const int N = in_sizes[4] / 6;

    transpose_all_kernel<<<NB_ALL, dim3(32, 8)>>>(f0, f1, f2, f3);
    rroi_main_kernel<<<dim3(N, OUT_H), 160>>>(rois, out);
}